// round 15
// baseline (speedup 1.0000x reference)
#include <cuda_runtime.h>
#include <cuda_fp16.h>
#include <cstdint>

// Problem constants
#define BB 4
#define CIN_X 64
#define COUT 128
#define DD 8
#define HH 128
#define WW 128
#define EE 256
#define OH 63
#define OW 63
#define HW (HH*WW)

// ---------------------------------------------------------------------------
// Device-global scratch. Channels-last (NDHWC) fp16 tensors.
// ---------------------------------------------------------------------------
__device__ float g_s1[BB*CIN_X];
__device__ float g_s2[BB*COUT];
__device__ __half g_x[BB*DD*HH*WW*64];            // x (for residual tap)
__device__ __half g_a[BB*DD*HH*WW*64];            // swish(x+s1)
__device__ __half g_h1[(size_t)BB*DD*HH*WW*128];  // after conv20 epi
__device__ __half g_h2[(size_t)BB*DD*HH*WW*128];  // after conv21 epi
// Pre-transposed + pre-swizzled weight tiles: 136 chunks x (128co x 64ci) fp16
// [0,27) conv20 taps; [27,81) conv21 (tap,cihalf); 81 res; [82,136) down (tap,cihalf)
__device__ __half g_w[136*8192];

__device__ __forceinline__ float swish_f(float v) {
    return v / (1.f + __expf(-v));
}

__device__ __forceinline__ uint32_t smem_u32(const void* p) {
    uint32_t a;
    asm("{ .reg .u64 t; cvta.to.shared.u64 t, %1; cvt.u32.u64 %0, t; }" : "=r"(a) : "l"(p));
    return a;
}

__device__ __forceinline__ uint32_t swz(uint32_t off) {
    return off ^ ((off >> 3) & 0x70);
}

__device__ __forceinline__ void cp_async16(uint32_t dst, const void* src, bool valid) {
    int sz = valid ? 16 : 0;
    asm volatile("cp.async.cg.shared.global [%0], [%1], 16, %2;"
                 :: "r"(dst), "l"(src), "r"(sz));
}

__device__ __forceinline__ void ldm4(uint32_t* r, uint32_t addr) {
    asm volatile("ldmatrix.sync.aligned.m8n8.x4.shared.b16 {%0,%1,%2,%3}, [%4];"
                 : "=r"(r[0]), "=r"(r[1]), "=r"(r[2]), "=r"(r[3]) : "r"(addr));
}

__device__ __forceinline__ void mma16816(float* d, const uint32_t* a, const uint32_t* b) {
    asm volatile(
        "mma.sync.aligned.m16n8k16.row.col.f32.f16.f16.f32 "
        "{%0,%1,%2,%3}, {%4,%5,%6,%7}, {%8,%9}, {%0,%1,%2,%3};"
        : "+f"(d[0]), "+f"(d[1]), "+f"(d[2]), "+f"(d[3])
        : "r"(a[0]), "r"(a[1]), "r"(a[2]), "r"(a[3]), "r"(b[0]), "r"(b[1]));
}

// ---------------------------------------------------------------------------
// Prep kernel: blocks 0..135 convert weight tiles (transposed, fp16, SW128);
// block 136 computes s1 = embed@d1_w+d1_b and s2 = context@d2_w+d2_b.
// ---------------------------------------------------------------------------
__global__ void prep_kernel(const float* __restrict__ w20,
                            const float* __restrict__ w21,
                            const float* __restrict__ resw,
                            const float* __restrict__ dwn,
                            const float* __restrict__ embed,
                            const float* __restrict__ context,
                            const float* __restrict__ d1w, const float* __restrict__ d1b,
                            const float* __restrict__ d2w, const float* __restrict__ d2b)
{
    int c = blockIdx.x;
    int tid = threadIdx.x;
    if (c < 136) {
        for (int i = tid; i < 8192; i += 256) {
            int co = i >> 6, ci = i & 63;
            float v;
            if (c < 27) {
                v = w20[(co*64 + ci)*27 + c];
            } else if (c < 81) {
                int cc = c - 27; int tap = cc >> 1, half = cc & 1;
                v = w21[(co*128 + half*64 + ci)*27 + tap];
            } else if (c == 81) {
                v = resw[co*64 + ci];
            } else {
                int cc = c - 82; int tap = cc >> 1, half = cc & 1;
                v = dwn[(co*128 + half*64 + ci)*27 + tap];
            }
            uint32_t sw = swz(co*128 + ci*2);
            *(__half*)((char*)g_w + (size_t)c*16384 + sw) = __float2half(v);
        }
    } else {
        // s1 (256 entries)
        {
            int n = tid >> 6, ch = tid & 63;
            float acc = d1b[ch];
            #pragma unroll 4
            for (int e = 0; e < EE; e++) acc += embed[n*EE + e] * d1w[e*CIN_X + ch];
            g_s1[tid] = acc;
        }
        // s2 (512 entries, 2 per thread)
        #pragma unroll
        for (int r = 0; r < 2; r++) {
            int t = tid + r*256;
            int n = t >> 7, ch = t & 127;
            float acc = d2b[ch];
            #pragma unroll 4
            for (int e = 0; e < EE; e++) acc += context[n*EE + e] * d2w[e*COUT + ch];
            g_s2[t] = acc;
        }
    }
}

// ---------------------------------------------------------------------------
// Kernel 2: NCDHW fp32 x -> channels-last fp16 x and act=swish(x+s1).
// (output loop packs channel pairs into one 4B store)
// ---------------------------------------------------------------------------
__global__ void __launch_bounds__(256) cvt_x_kernel(const float* __restrict__ x)
{
    __shared__ float sm[64*133];
    const int h  = blockIdx.x;
    const int nd = blockIdx.y;
    const int n  = nd >> 3, d = nd & 7;
    const int tid = threadIdx.x;

    for (int i = tid; i < 64*128; i += 256) {
        int ci = i >> 7, w = i & 127;
        sm[ci*133 + w] = x[((size_t)(n*64 + ci)*8 + d)*HW + h*128 + w];
    }
    __syncthreads();
    size_t base = ((size_t)nd*128 + h) * 128 * 64;
    for (int i = tid; i < 64*128/2; i += 256) {
        int w = i >> 5, cp = (i & 31) * 2;
        float v0 = sm[cp*133 + w];
        float v1 = sm[(cp + 1)*133 + w];
        float a0 = swish_f(v0 + g_s1[n*64 + cp]);
        float a1 = swish_f(v1 + g_s1[n*64 + cp + 1]);
        size_t o = base + (size_t)w*64 + cp;
        *(__half2*)(g_x + o) = __floats2half2_rn(v0, v1);
        *(__half2*)(g_a + o) = __floats2half2_rn(a0, a1);
    }
}

// ---------------------------------------------------------------------------
// Implicit-GEMM conv, single-pass fp16 mma.sync. 256 threads, 8 warps (4M x 2N),
// warp tile 32x32. CTA tile M=128 px x N=64 co (co half via blockIdx.x -> the
// two co-half CTAs are launch-adjacent and share A rows through L2), 2 CTA/SM.
// Padding chunks are skipped with a COMPACT cursor (no wasted barrier rounds).
// MODE 0: conv20. 9 plane-chunks (kd,kh), K=192 each (3 kw taps).
// MODE 1: conv21. 18 plane-half-chunks + 1 residual chunk.
// MODE 2: down. 18 plane-half-chunks, K=192. A rows stored PARITY-SPLIT:
//         kw=0 -> s=ow, kw=1 -> s=64+ow, kw=2 -> s=ow+1 (conflict-free).
// MODE 0/1 epilogue staged through smem (stride-72 pad, conflict-free) for
// fully-coalesced 16B global stores.
// ---------------------------------------------------------------------------
#define STAGE_P   41984   // A 17408 (132 rows x 128B) | B 24576 (3 taps x 64co)
#define STAGE_D   57344   // A 32768 (256 row slots)   | B 24576

template<int MODE>
__global__ void __launch_bounds__(256, 2) conv_mma(const float* __restrict__ bias,
                                                   float* __restrict__ outp)
{
    extern __shared__ __align__(1024) char smem[];
    constexpr int NCHUNK = (MODE == 0) ? 9 : (MODE == 1) ? 19 : 18;
    constexpr int STAGE  = (MODE == 2) ? STAGE_D : STAGE_P;
    constexpr int ABYTES = (MODE == 2) ? 32768 : 17408;

    const uint32_t sb = smem_u32(smem);
    const int tid  = threadIdx.x;
    const int wid  = tid >> 5;
    const int lane = tid & 31;
    const int cob = blockIdx.x;      // co half: 0 or 1 (fastest -> L2 pairing)
    const int hq  = blockIdx.y;      // h (MODE 0/1); oh-pair index (MODE 2)
    const int nd  = blockIdx.z, n = nd >> 3, d = nd & 7;

    const int m0 = (wid & 3) * 32;
    const int n0 = (wid >> 2) * 32;
    const int sub = lane >> 3, rl = lane & 7;

    float acc[2][4][4];
    #pragma unroll
    for (int a = 0; a < 2; a++)
        #pragma unroll
        for (int b = 0; b < 4; b++)
            #pragma unroll
            for (int q = 0; q < 4; q++) acc[a][b][q] = 0.f;

    // Chunk validity: false when the whole input plane is padding.
    auto chunkValid = [&](int c) -> bool {
        if (MODE == 1 && c == 18) return true;          // residual tap
        int pc = (MODE == 0) ? c : (c >> 1);
        int kd = pc / 3, kh = pc % 3;
        if ((unsigned)(d + kd - 1) >= 8u) return false;
        if (MODE != 2) {
            if ((unsigned)(hq + kh - 1) >= 128u) return false;
        }
        return true;
    };
    auto nextValid = [&](int c) -> int {
        for (int t = c + 1; t < NCHUNK; t++)
            if (chunkValid(t)) return t;
        return -1;
    };

    auto stage = [&](int c, int buf) {
        uint32_t aS = sb + buf*STAGE;
        uint32_t bS = aS + ABYTES;
        const char* dummy = (const char*)g_w;

        if constexpr (MODE == 2) {
            int pc = c >> 1, half = c & 1;
            int kd = pc / 3, kh = pc % 3;
            int id = d + kd - 1;
            const char* pl = (const char*)(g_h2 + ((size_t)(n*8 + id)*HW)*128 + half*64);
            // A: slot r = ohl*128 + s; s parity-split: iw = (s<64)? 2s : 2(s-64)+1
            #pragma unroll
            for (int t = 0; t < 8; t++) {
                int i = tid + t*256;
                int r = i >> 3, q = i & 7;
                int ohl = r >> 7, s = r & 127;
                int iw = (s < 64) ? (2*s) : (2*(s - 64) + 1);
                int oh = hq*2 + ohl;
                int ih = oh*2 + kh;
                bool v = (iw < 127) && (oh < 63);
                size_t off = ((size_t)ih*128 + iw)*256 + q*16;
                cp_async16(aS + swz(r*128 + q*16), v ? pl + off : dummy, v);
            }
            // B: 3 kw taps x 8KB co-half
            #pragma unroll
            for (int t = 0; t < 6; t++) {
                int i = tid + t*256;
                int kw = i >> 9, j = i & 511;
                int wchunk = 82 + (pc*3 + kw)*2 + half;
                const char* wS = (const char*)g_w + (size_t)wchunk*16384 + cob*8192;
                cp_async16(bS + i*16, wS + j*16, true);
            }
        } else {
            bool isRes = (MODE == 1) && (c == 18);
            if (!isRes) {
                int pc, half, srcStride;
                if (MODE == 0) { pc = c; half = 0; srcStride = 128; }
                else           { pc = c >> 1; half = c & 1; srcStride = 256; }
                int kd = pc / 3, kh = pc % 3;
                int id = d + kd - 1;
                int ih = hq + kh - 1;
                const char* src;
                {
                    size_t pb = ((size_t)((n*8 + id)*128 + ih)) * 128;
                    if (MODE == 0) src = (const char*)(g_a  + pb*64);
                    else           src = (const char*)(g_h1 + pb*128 + half*64);
                }
                // A: rows 0..129 <-> iw -1..128 (zero-filled halo); 1040 = 4*256 + 16
                #pragma unroll
                for (int t = 0; t < 4; t++) {
                    int i = tid + t*256;
                    int r = i >> 3, q = i & 7;
                    int iw = r - 1;
                    bool v = ((unsigned)iw < 128u);
                    cp_async16(aS + swz(r*128 + q*16),
                               v ? src + (size_t)iw*srcStride + q*16 : dummy, v);
                }
                if (tid < 16) {
                    int i = 1024 + tid;
                    int r = i >> 3, q = i & 7;
                    int iw = r - 1;
                    bool v = ((unsigned)iw < 128u);
                    cp_async16(aS + swz(r*128 + q*16),
                               v ? src + (size_t)iw*srcStride + q*16 : dummy, v);
                }
                // B: 3 kw taps, each 8KB (this CTA's co-half)
                #pragma unroll
                for (int t = 0; t < 6; t++) {
                    int i = tid + t*256;
                    int kw = i >> 9, j = i & 511;
                    int wchunk = (MODE == 0) ? (pc*3 + kw)
                                             : 27 + ((pc*3 + kw)*2 + half);
                    const char* wS = (const char*)g_w + (size_t)wchunk*16384 + cob*8192;
                    cp_async16(bS + i*16, wS + j*16, true);
                }
            } else {
                // residual 1x1x1 tap
                const char* src = (const char*)(g_x + ((size_t)(nd*128 + hq))*128*64);
                #pragma unroll
                for (int t = 0; t < 4; t++) {
                    int i = tid + t*256;
                    int r = i >> 3, q = i & 7;
                    cp_async16(aS + swz(r*128 + q*16), src + (size_t)r*128 + q*16, true);
                }
                const char* wS = (const char*)g_w + (size_t)81*16384 + cob*8192;
                #pragma unroll
                for (int t = 0; t < 2; t++) {
                    int i = (tid + t*256)*16;
                    cp_async16(bS + i, wS + i, true);
                }
            }
        }
    };

    // compact cursors over valid chunks
    int cur = chunkValid(0) ? 0 : nextValid(0);
    int nxt = (cur >= 0) ? nextValid(cur) : -1;

    if (cur >= 0) stage(cur, 0);
    asm volatile("cp.async.commit_group;");

    int buf = 0;
    while (cur >= 0) {
        asm volatile("cp.async.wait_group 0;" ::: "memory");
        __syncthreads();
        if (nxt >= 0) stage(nxt, buf ^ 1);
        asm volatile("cp.async.commit_group;");

        uint32_t aS = sb + buf*STAGE;
        uint32_t bS = aS + ABYTES;
        bool isRes = (MODE == 1) && (cur == 18);

        auto doTap = [&](int tap) {
            #pragma unroll
            for (int kk = 0; kk < 4; kk++) {
                const int k0b = kk*32;
                uint32_t aF[2][4], bF[2][4];
                #pragma unroll
                for (int fm = 0; fm < 2; fm++) {
                    uint32_t row;
                    if constexpr (MODE == 2) {
                        int p = m0 + fm*16 + (sub & 1)*8 + rl;
                        int ohl = p >> 6, ow = p & 63;
                        int s = (tap == 0) ? ow : (tap == 1) ? (64 + ow) : (ow + 1);
                        row = ohl*128 + s;
                    } else {
                        row = m0 + fm*16 + (sub & 1)*8 + rl + tap;
                    }
                    ldm4(aF[fm], aS + swz(row*128 + k0b + (sub >> 1)*16));
                }
                #pragma unroll
                for (int nb = 0; nb < 2; nb++) {
                    uint32_t so = swz((n0 + nb*16 + (sub >> 1)*8 + rl)*128 + k0b + (sub & 1)*16);
                    ldm4(bF[nb], bS + tap*8192 + so);
                }
                #pragma unroll
                for (int fm = 0; fm < 2; fm++)
                    #pragma unroll
                    for (int j = 0; j < 4; j++)
                        mma16816(acc[fm][j], aF[fm], &bF[j >> 1][(j & 1)*2]);
            }
        };
        if (isRes) {
            doTap(0);
        } else {
            doTap(0); doTap(1); doTap(2);
        }

        cur = nxt;
        nxt = (cur >= 0) ? nextValid(cur) : -1;
        buf ^= 1;
    }
    asm volatile("cp.async.wait_all;" ::: "memory");

    // ---- epilogue ----
    const size_t rowBase = (size_t)(nd*128 + hq) * 128;
    if constexpr (MODE == 2) {
        #pragma unroll
        for (int fm = 0; fm < 2; fm++) {
            #pragma unroll
            for (int j = 0; j < 4; j++) {
                int c0 = cob*64 + n0 + j*8 + (lane & 3)*2;
                int r0 = m0 + fm*16 + (lane >> 2);
                float b0v = bias[c0], b1v = bias[c0 + 1];
                #pragma unroll
                for (int rr = 0; rr < 2; rr++) {
                    int row = r0 + rr*8;
                    float v0 = acc[fm][j][rr*2 + 0] + b0v;
                    float v1 = acc[fm][j][rr*2 + 1] + b1v;
                    int ohl = row >> 6, ow = row & 63;
                    int oh = hq*2 + ohl;
                    if (ow < OW && oh < OH) {
                        size_t ob = ((size_t)(n*128 + c0)*8 + d)*(OH*OW) + oh*OW + ow;
                        outp[ob] = v0;
                        outp[ob + (size_t)8*(OH*OW)] = v1;
                    }
                }
            }
        }
    } else {
        // stage results in smem [128 rows][72 halfs] (stride 144B: conflict-free
        // both for the 4B scattered writes and the 16B coalescing reads),
        // then write 16B fully-coalesced lines to global.
        __syncthreads();                     // stage buffers are dead now
        __half* eb = (__half*)smem;
        #pragma unroll
        for (int fm = 0; fm < 2; fm++) {
            #pragma unroll
            for (int j = 0; j < 4; j++) {
                int lc = n0 + j*8 + (lane & 3)*2;     // local col 0..63
                int c0 = cob*64 + lc;
                int r0 = m0 + fm*16 + (lane >> 2);
                float b0v = bias[c0], b1v = bias[c0 + 1];
                #pragma unroll
                for (int rr = 0; rr < 2; rr++) {
                    int row = r0 + rr*8;
                    float v0 = acc[fm][j][rr*2 + 0] + b0v;
                    float v1 = acc[fm][j][rr*2 + 1] + b1v;
                    if (MODE == 0) {
                        v0 = swish_f(v0) * g_s2[n*128 + c0];
                        v1 = swish_f(v1) * g_s2[n*128 + c0 + 1];
                    } else {
                        v0 = swish_f(v0);
                        v1 = swish_f(v1);
                    }
                    __half h0 = __float2half(v0);
                    __half h1 = __float2half(v1);
                    uint32_t hp = (uint32_t)__half_as_ushort(h1) << 16 |
                                  __half_as_ushort(h0);
                    *(uint32_t*)&eb[row*72 + lc] = hp;
                }
            }
        }
        __syncthreads();
        __half* dst = (MODE == 0) ? g_h1 : g_h2;
        #pragma unroll
        for (int t = 0; t < 4; t++) {
            int i = tid + t*256;             // 1024 = 128 rows x 8 q
            int r = i >> 3, q = i & 7;
            *(uint4*)&dst[(rowBase + r)*128 + cob*64 + q*8] =
                *(const uint4*)&eb[r*72 + q*8];
        }
    }
}

// ---------------------------------------------------------------------------
extern "C" void kernel_launch(void* const* d_in, const int* in_sizes, int n_in,
                              void* d_out, int out_size)
{
    const float* x       = (const float*)d_in[0];
    const float* embed   = (const float*)d_in[1];
    const float* context = (const float*)d_in[2];
    const float* w20     = (const float*)d_in[3];
    const float* b20     = (const float*)d_in[4];
    const float* w21     = (const float*)d_in[5];
    const float* d1_w    = (const float*)d_in[6];
    const float* d1_b    = (const float*)d_in[7];
    const float* d2_w    = (const float*)d_in[8];
    const float* d2_b    = (const float*)d_in[9];
    const float* res_w   = (const float*)d_in[10];
    const float* res_b   = (const float*)d_in[11];
    const float* down_w  = (const float*)d_in[12];
    const float* down_b  = (const float*)d_in[13];
    float* out = (float*)d_out;

    const int smemP = 2*STAGE_P;   // 83968
    const int smemD = 2*STAGE_D;   // 114688
    cudaFuncSetAttribute(conv_mma<0>, cudaFuncAttributeMaxDynamicSharedMemorySize, smemP);
    cudaFuncSetAttribute(conv_mma<1>, cudaFuncAttributeMaxDynamicSharedMemorySize, smemP);
    cudaFuncSetAttribute(conv_mma<2>, cudaFuncAttributeMaxDynamicSharedMemorySize, smemD);

    prep_kernel<<<137, 256>>>(w20, w21, res_w, down_w,
                              embed, context, d1_w, d1_b, d2_w, d2_b);
    cvt_x_kernel<<<dim3(HH, BB*DD), 256>>>(x);

    conv_mma<0><<<dim3(2, HH, BB*DD), 256, smemP>>>(b20,    nullptr);
    conv_mma<1><<<dim3(2, HH, BB*DD), 256, smemP>>>(res_b,  nullptr);
    conv_mma<2><<<dim3(2, 32, BB*DD), 256, smemD>>>(down_b, out);
}

// round 16
// speedup vs baseline: 1.5338x; 1.5338x over previous
#include <cuda_runtime.h>
#include <cuda_fp16.h>
#include <cstdint>

// Problem constants
#define BB 4
#define CIN_X 64
#define COUT 128
#define DD 8
#define HH 128
#define WW 128
#define EE 256
#define OH 63
#define OW 63
#define HW (HH*WW)

// ---------------------------------------------------------------------------
// Device-global scratch. Channels-last (NDHWC) fp16 tensors.
// ---------------------------------------------------------------------------
__device__ float g_s1[BB*CIN_X];
__device__ float g_s2[BB*COUT];
__device__ __half g_x[BB*DD*HH*WW*64];            // x (for residual tap)
__device__ __half g_a[BB*DD*HH*WW*64];            // swish(x+s1)
__device__ __half g_h1[(size_t)BB*DD*HH*WW*128];  // after conv20 epi
__device__ __half g_h2[(size_t)BB*DD*HH*WW*128];  // after conv21 epi
// Pre-transposed + pre-swizzled weight tiles: 136 chunks x (128co x 64ci) fp16
// [0,27) conv20 taps; [27,81) conv21 (tap,cihalf); 81 res; [82,136) down (tap,cihalf)
__device__ __half g_w[136*8192];

__device__ __forceinline__ float swish_f(float v) {
    return v / (1.f + __expf(-v));
}

__device__ __forceinline__ uint32_t smem_u32(const void* p) {
    uint32_t a;
    asm("{ .reg .u64 t; cvta.to.shared.u64 t, %1; cvt.u32.u64 %0, t; }" : "=r"(a) : "l"(p));
    return a;
}

__device__ __forceinline__ uint32_t swz(uint32_t off) {
    return off ^ ((off >> 3) & 0x70);
}

__device__ __forceinline__ void cp_async16(uint32_t dst, const void* src, bool valid) {
    int sz = valid ? 16 : 0;
    asm volatile("cp.async.cg.shared.global [%0], [%1], 16, %2;"
                 :: "r"(dst), "l"(src), "r"(sz));
}

__device__ __forceinline__ void ldm4(uint32_t* r, uint32_t addr) {
    asm volatile("ldmatrix.sync.aligned.m8n8.x4.shared.b16 {%0,%1,%2,%3}, [%4];"
                 : "=r"(r[0]), "=r"(r[1]), "=r"(r[2]), "=r"(r[3]) : "r"(addr));
}

__device__ __forceinline__ void mma16816(float* d, const uint32_t* a, const uint32_t* b) {
    asm volatile(
        "mma.sync.aligned.m16n8k16.row.col.f32.f16.f16.f32 "
        "{%0,%1,%2,%3}, {%4,%5,%6,%7}, {%8,%9}, {%0,%1,%2,%3};"
        : "+f"(d[0]), "+f"(d[1]), "+f"(d[2]), "+f"(d[3])
        : "r"(a[0]), "r"(a[1]), "r"(a[2]), "r"(a[3]), "r"(b[0]), "r"(b[1]));
}

// ---------------------------------------------------------------------------
// Prep kernel: blocks 0..135 convert weight tiles (transposed, fp16, SW128);
// block 136 computes s1 = embed@d1_w+d1_b and s2 = context@d2_w+d2_b.
// ---------------------------------------------------------------------------
__global__ void prep_kernel(const float* __restrict__ w20,
                            const float* __restrict__ w21,
                            const float* __restrict__ resw,
                            const float* __restrict__ dwn,
                            const float* __restrict__ embed,
                            const float* __restrict__ context,
                            const float* __restrict__ d1w, const float* __restrict__ d1b,
                            const float* __restrict__ d2w, const float* __restrict__ d2b)
{
    int c = blockIdx.x;
    int tid = threadIdx.x;
    if (c < 136) {
        for (int i = tid; i < 8192; i += 256) {
            int co = i >> 6, ci = i & 63;
            float v;
            if (c < 27) {
                v = w20[(co*64 + ci)*27 + c];
            } else if (c < 81) {
                int cc = c - 27; int tap = cc >> 1, half = cc & 1;
                v = w21[(co*128 + half*64 + ci)*27 + tap];
            } else if (c == 81) {
                v = resw[co*64 + ci];
            } else {
                int cc = c - 82; int tap = cc >> 1, half = cc & 1;
                v = dwn[(co*128 + half*64 + ci)*27 + tap];
            }
            uint32_t sw = swz(co*128 + ci*2);
            *(__half*)((char*)g_w + (size_t)c*16384 + sw) = __float2half(v);
        }
    } else {
        // s1 (256 entries)
        {
            int n = tid >> 6, ch = tid & 63;
            float acc = d1b[ch];
            #pragma unroll 4
            for (int e = 0; e < EE; e++) acc += embed[n*EE + e] * d1w[e*CIN_X + ch];
            g_s1[tid] = acc;
        }
        // s2 (512 entries, 2 per thread)
        #pragma unroll
        for (int r = 0; r < 2; r++) {
            int t = tid + r*256;
            int n = t >> 7, ch = t & 127;
            float acc = d2b[ch];
            #pragma unroll 4
            for (int e = 0; e < EE; e++) acc += context[n*EE + e] * d2w[e*COUT + ch];
            g_s2[t] = acc;
        }
    }
}

// ---------------------------------------------------------------------------
// Kernel 2: NCDHW fp32 x -> channels-last fp16 x and act=swish(x+s1).
// (output loop packs channel pairs into one 4B store)
// ---------------------------------------------------------------------------
__global__ void __launch_bounds__(256) cvt_x_kernel(const float* __restrict__ x)
{
    __shared__ float sm[64*133];
    const int h  = blockIdx.x;
    const int nd = blockIdx.y;
    const int n  = nd >> 3, d = nd & 7;
    const int tid = threadIdx.x;

    for (int i = tid; i < 64*128; i += 256) {
        int ci = i >> 7, w = i & 127;
        sm[ci*133 + w] = x[((size_t)(n*64 + ci)*8 + d)*HW + h*128 + w];
    }
    __syncthreads();
    size_t base = ((size_t)nd*128 + h) * 128 * 64;
    for (int i = tid; i < 64*128/2; i += 256) {
        int w = i >> 5, cp = (i & 31) * 2;
        float v0 = sm[cp*133 + w];
        float v1 = sm[(cp + 1)*133 + w];
        float a0 = swish_f(v0 + g_s1[n*64 + cp]);
        float a1 = swish_f(v1 + g_s1[n*64 + cp + 1]);
        size_t o = base + (size_t)w*64 + cp;
        *(__half2*)(g_x + o) = __floats2half2_rn(v0, v1);
        *(__half2*)(g_a + o) = __floats2half2_rn(a0, a1);
    }
}

// ---------------------------------------------------------------------------
// Implicit-GEMM conv, single-pass fp16 mma.sync. 256 threads, 8 warps (4M x 2N),
// warp tile 32x32. CTA tile M=128 px x N=64 co (co half via blockIdx.x -> the
// two co-half CTAs are launch-adjacent and share A rows through L2), 2 CTA/SM.
// Padding chunks are skipped with a COMPACT cursor (no wasted barrier rounds).
// MODE 0: conv20. 9 plane-chunks (kd,kh), K=192 each (3 kw taps).
// MODE 1: conv21. 18 plane-half-chunks + 1 residual chunk.
// MODE 2: down. 18 plane-half-chunks, K=192. A rows stored PARITY-SPLIT:
//         kw=0 -> s=ow, kw=1 -> s=64+ow, kw=2 -> s=ow+1 (conflict-free).
// MODE 0/1 epilogue staged through smem (stride-72 pad, conflict-free) for
// fully-coalesced 16B global stores.
// ---------------------------------------------------------------------------
#define STAGE_P   41984   // A 17408 (132 rows x 128B) | B 24576 (3 taps x 64co)
#define STAGE_D   57344   // A 32768 (256 row slots)   | B 24576

template<int MODE>
__global__ void __launch_bounds__(256, 2) conv_mma(const float* __restrict__ bias,
                                                   float* __restrict__ outp)
{
    extern __shared__ __align__(1024) char smem[];
    constexpr int NCHUNK = (MODE == 0) ? 9 : (MODE == 1) ? 19 : 18;
    constexpr int STAGE  = (MODE == 2) ? STAGE_D : STAGE_P;
    constexpr int ABYTES = (MODE == 2) ? 32768 : 17408;

    const uint32_t sb = smem_u32(smem);
    const int tid  = threadIdx.x;
    const int wid  = tid >> 5;
    const int lane = tid & 31;
    const int cob = blockIdx.x;      // co half: 0 or 1 (fastest -> L2 pairing)
    const int hq  = blockIdx.y;      // h (MODE 0/1); oh-pair index (MODE 2)
    const int nd  = blockIdx.z, n = nd >> 3, d = nd & 7;

    const int m0 = (wid & 3) * 32;
    const int n0 = (wid >> 2) * 32;
    const int sub = lane >> 3, rl = lane & 7;

    float acc[2][4][4];
    #pragma unroll
    for (int a = 0; a < 2; a++)
        #pragma unroll
        for (int b = 0; b < 4; b++)
            #pragma unroll
            for (int q = 0; q < 4; q++) acc[a][b][q] = 0.f;

    // Chunk validity: false when the whole input plane is padding.
    auto chunkValid = [&](int c) -> bool {
        if (MODE == 1 && c == 18) return true;          // residual tap
        int pc = (MODE == 0) ? c : (c >> 1);
        int kd = pc / 3, kh = pc % 3;
        if ((unsigned)(d + kd - 1) >= 8u) return false;
        if (MODE != 2) {
            if ((unsigned)(hq + kh - 1) >= 128u) return false;
        }
        return true;
    };
    auto nextValid = [&](int c) -> int {
        for (int t = c + 1; t < NCHUNK; t++)
            if (chunkValid(t)) return t;
        return -1;
    };

    auto stage = [&](int c, int buf) {
        uint32_t aS = sb + buf*STAGE;
        uint32_t bS = aS + ABYTES;
        const char* dummy = (const char*)g_w;

        if constexpr (MODE == 2) {
            int pc = c >> 1, half = c & 1;
            int kd = pc / 3, kh = pc % 3;
            int id = d + kd - 1;
            const char* pl = (const char*)(g_h2 + ((size_t)(n*8 + id)*HW)*128 + half*64);
            // A: slot r = ohl*128 + s; s parity-split: iw = (s<64)? 2s : 2(s-64)+1
            #pragma unroll
            for (int t = 0; t < 8; t++) {
                int i = tid + t*256;
                int r = i >> 3, q = i & 7;
                int ohl = r >> 7, s = r & 127;
                int iw = (s < 64) ? (2*s) : (2*(s - 64) + 1);
                int oh = hq*2 + ohl;
                int ih = oh*2 + kh;
                bool v = (iw < 127) && (oh < 63);
                size_t off = ((size_t)ih*128 + iw)*256 + q*16;
                cp_async16(aS + swz(r*128 + q*16), v ? pl + off : dummy, v);
            }
            // B: 3 kw taps x 8KB co-half
            #pragma unroll
            for (int t = 0; t < 6; t++) {
                int i = tid + t*256;
                int kw = i >> 9, j = i & 511;
                int wchunk = 82 + (pc*3 + kw)*2 + half;
                const char* wS = (const char*)g_w + (size_t)wchunk*16384 + cob*8192;
                cp_async16(bS + i*16, wS + j*16, true);
            }
        } else {
            bool isRes = (MODE == 1) && (c == 18);
            if (!isRes) {
                int pc, half, srcStride;
                if (MODE == 0) { pc = c; half = 0; srcStride = 128; }
                else           { pc = c >> 1; half = c & 1; srcStride = 256; }
                int kd = pc / 3, kh = pc % 3;
                int id = d + kd - 1;
                int ih = hq + kh - 1;
                const char* src;
                {
                    size_t pb = ((size_t)((n*8 + id)*128 + ih)) * 128;
                    if (MODE == 0) src = (const char*)(g_a  + pb*64);
                    else           src = (const char*)(g_h1 + pb*128 + half*64);
                }
                // A: rows 0..129 <-> iw -1..128 (zero-filled halo); 1040 = 4*256 + 16
                #pragma unroll
                for (int t = 0; t < 4; t++) {
                    int i = tid + t*256;
                    int r = i >> 3, q = i & 7;
                    int iw = r - 1;
                    bool v = ((unsigned)iw < 128u);
                    cp_async16(aS + swz(r*128 + q*16),
                               v ? src + (size_t)iw*srcStride + q*16 : dummy, v);
                }
                if (tid < 16) {
                    int i = 1024 + tid;
                    int r = i >> 3, q = i & 7;
                    int iw = r - 1;
                    bool v = ((unsigned)iw < 128u);
                    cp_async16(aS + swz(r*128 + q*16),
                               v ? src + (size_t)iw*srcStride + q*16 : dummy, v);
                }
                // B: 3 kw taps, each 8KB (this CTA's co-half)
                #pragma unroll
                for (int t = 0; t < 6; t++) {
                    int i = tid + t*256;
                    int kw = i >> 9, j = i & 511;
                    int wchunk = (MODE == 0) ? (pc*3 + kw)
                                             : 27 + ((pc*3 + kw)*2 + half);
                    const char* wS = (const char*)g_w + (size_t)wchunk*16384 + cob*8192;
                    cp_async16(bS + i*16, wS + j*16, true);
                }
            } else {
                // residual 1x1x1 tap
                const char* src = (const char*)(g_x + ((size_t)(nd*128 + hq))*128*64);
                #pragma unroll
                for (int t = 0; t < 4; t++) {
                    int i = tid + t*256;
                    int r = i >> 3, q = i & 7;
                    cp_async16(aS + swz(r*128 + q*16), src + (size_t)r*128 + q*16, true);
                }
                const char* wS = (const char*)g_w + (size_t)81*16384 + cob*8192;
                #pragma unroll
                for (int t = 0; t < 2; t++) {
                    int i = (tid + t*256)*16;
                    cp_async16(bS + i, wS + i, true);
                }
            }
        }
    };

    // compact cursors over valid chunks
    int cur = chunkValid(0) ? 0 : nextValid(0);
    int nxt = (cur >= 0) ? nextValid(cur) : -1;

    if (cur >= 0) stage(cur, 0);
    asm volatile("cp.async.commit_group;");

    int buf = 0;
    while (cur >= 0) {
        asm volatile("cp.async.wait_group 0;" ::: "memory");
        __syncthreads();
        if (nxt >= 0) stage(nxt, buf ^ 1);
        asm volatile("cp.async.commit_group;");

        uint32_t aS = sb + buf*STAGE;
        uint32_t bS = aS + ABYTES;
        bool isRes = (MODE == 1) && (cur == 18);

        auto doTap = [&](int tap) {
            #pragma unroll
            for (int kk = 0; kk < 4; kk++) {
                const int k0b = kk*32;
                uint32_t aF[2][4], bF[2][4];
                #pragma unroll
                for (int fm = 0; fm < 2; fm++) {
                    uint32_t row;
                    if constexpr (MODE == 2) {
                        int p = m0 + fm*16 + (sub & 1)*8 + rl;
                        int ohl = p >> 6, ow = p & 63;
                        int s = (tap == 0) ? ow : (tap == 1) ? (64 + ow) : (ow + 1);
                        row = ohl*128 + s;
                    } else {
                        row = m0 + fm*16 + (sub & 1)*8 + rl + tap;
                    }
                    ldm4(aF[fm], aS + swz(row*128 + k0b + (sub >> 1)*16));
                }
                #pragma unroll
                for (int nb = 0; nb < 2; nb++) {
                    uint32_t so = swz((n0 + nb*16 + (sub >> 1)*8 + rl)*128 + k0b + (sub & 1)*16);
                    ldm4(bF[nb], bS + tap*8192 + so);
                }
                #pragma unroll
                for (int fm = 0; fm < 2; fm++)
                    #pragma unroll
                    for (int j = 0; j < 4; j++)
                        mma16816(acc[fm][j], aF[fm], &bF[j >> 1][(j & 1)*2]);
            }
        };
        if (isRes) {
            doTap(0);
        } else {
            doTap(0); doTap(1); doTap(2);
        }

        cur = nxt;
        nxt = (cur >= 0) ? nextValid(cur) : -1;
        buf ^= 1;
    }
    asm volatile("cp.async.wait_all;" ::: "memory");

    // ---- epilogue ----
    const size_t rowBase = (size_t)(nd*128 + hq) * 128;
    if constexpr (MODE == 2) {
        #pragma unroll
        for (int fm = 0; fm < 2; fm++) {
            #pragma unroll
            for (int j = 0; j < 4; j++) {
                int c0 = cob*64 + n0 + j*8 + (lane & 3)*2;
                int r0 = m0 + fm*16 + (lane >> 2);
                float b0v = bias[c0], b1v = bias[c0 + 1];
                #pragma unroll
                for (int rr = 0; rr < 2; rr++) {
                    int row = r0 + rr*8;
                    float v0 = acc[fm][j][rr*2 + 0] + b0v;
                    float v1 = acc[fm][j][rr*2 + 1] + b1v;
                    int ohl = row >> 6, ow = row & 63;
                    int oh = hq*2 + ohl;
                    if (ow < OW && oh < OH) {
                        size_t ob = ((size_t)(n*128 + c0)*8 + d)*(OH*OW) + oh*OW + ow;
                        outp[ob] = v0;
                        outp[ob + (size_t)8*(OH*OW)] = v1;
                    }
                }
            }
        }
    } else {
        // stage results in smem [128 rows][72 halfs] (stride 144B: conflict-free
        // both for the 4B scattered writes and the 16B coalescing reads),
        // then write 16B fully-coalesced lines to global.
        __syncthreads();                     // stage buffers are dead now
        __half* eb = (__half*)smem;
        #pragma unroll
        for (int fm = 0; fm < 2; fm++) {
            #pragma unroll
            for (int j = 0; j < 4; j++) {
                int lc = n0 + j*8 + (lane & 3)*2;     // local col 0..63
                int c0 = cob*64 + lc;
                int r0 = m0 + fm*16 + (lane >> 2);
                float b0v = bias[c0], b1v = bias[c0 + 1];
                #pragma unroll
                for (int rr = 0; rr < 2; rr++) {
                    int row = r0 + rr*8;
                    float v0 = acc[fm][j][rr*2 + 0] + b0v;
                    float v1 = acc[fm][j][rr*2 + 1] + b1v;
                    if (MODE == 0) {
                        v0 = swish_f(v0) * g_s2[n*128 + c0];
                        v1 = swish_f(v1) * g_s2[n*128 + c0 + 1];
                    } else {
                        v0 = swish_f(v0);
                        v1 = swish_f(v1);
                    }
                    __half h0 = __float2half(v0);
                    __half h1 = __float2half(v1);
                    uint32_t hp = (uint32_t)__half_as_ushort(h1) << 16 |
                                  __half_as_ushort(h0);
                    *(uint32_t*)&eb[row*72 + lc] = hp;
                }
            }
        }
        __syncthreads();
        __half* dst = (MODE == 0) ? g_h1 : g_h2;
        #pragma unroll
        for (int t = 0; t < 4; t++) {
            int i = tid + t*256;             // 1024 = 128 rows x 8 q
            int r = i >> 3, q = i & 7;
            *(uint4*)&dst[(rowBase + r)*128 + cob*64 + q*8] =
                *(const uint4*)&eb[r*72 + q*8];
        }
    }
}

// ---------------------------------------------------------------------------
extern "C" void kernel_launch(void* const* d_in, const int* in_sizes, int n_in,
                              void* d_out, int out_size)
{
    const float* x       = (const float*)d_in[0];
    const float* embed   = (const float*)d_in[1];
    const float* context = (const float*)d_in[2];
    const float* w20     = (const float*)d_in[3];
    const float* b20     = (const float*)d_in[4];
    const float* w21     = (const float*)d_in[5];
    const float* d1_w    = (const float*)d_in[6];
    const float* d1_b    = (const float*)d_in[7];
    const float* d2_w    = (const float*)d_in[8];
    const float* d2_b    = (const float*)d_in[9];
    const float* res_w   = (const float*)d_in[10];
    const float* res_b   = (const float*)d_in[11];
    const float* down_w  = (const float*)d_in[12];
    const float* down_b  = (const float*)d_in[13];
    float* out = (float*)d_out;

    const int smemP = 2*STAGE_P;   // 83968
    const int smemD = 2*STAGE_D;   // 114688
    cudaFuncSetAttribute(conv_mma<0>, cudaFuncAttributeMaxDynamicSharedMemorySize, smemP);
    cudaFuncSetAttribute(conv_mma<1>, cudaFuncAttributeMaxDynamicSharedMemorySize, smemP);
    cudaFuncSetAttribute(conv_mma<2>, cudaFuncAttributeMaxDynamicSharedMemorySize, smemD);

    prep_kernel<<<137, 256>>>(w20, w21, res_w, down_w,
                              embed, context, d1_w, d1_b, d2_w, d2_b);
    cvt_x_kernel<<<dim3(HH, BB*DD), 256>>>(x);

    conv_mma<0><<<dim3(2, HH, BB*DD), 256, smemP>>>(b20,    nullptr);
    conv_mma<1><<<dim3(2, HH, BB*DD), 256, smemP>>>(res_b,  nullptr);
    conv_mma<2><<<dim3(2, 32, BB*DD), 256, smemD>>>(down_b, out);
}